// round 2
// baseline (speedup 1.0000x reference)
#include <cuda_runtime.h>

#define NN 100000
#define EE 1200000
#define GG 128
#define HH 64

// ---------------- static device buffers (no allocation allowed) ----------------
__device__ int g_deg[NN + 1];
__device__ int g_row[NN + 1];
__device__ int g_cur[NN + 1];
__device__ int g_src[EE];
__device__ int g_bsums[256];
__device__ int g_cntg[GG];
__device__ int g_e64, g_b64;
__device__ float g_Q[(size_t)NN * HH];
__device__ float g_K[(size_t)NN * HH];
__device__ float g_V[(size_t)NN * HH];
__device__ float g_S[(size_t)NN * HH];
__device__ float g_h1[(size_t)NN * HH];
__device__ float g_h2[(size_t)NN * HH];

// ---------------- helpers ----------------
__device__ __forceinline__ unsigned long long pack2(float a, float b) {
    unsigned long long r;
    asm("mov.b64 %0, {%1, %2};" : "=l"(r) : "r"(__float_as_uint(a)), "r"(__float_as_uint(b)));
    return r;
}
__device__ __forceinline__ void unpack2(unsigned long long v, float& a, float& b) {
    unsigned int lo, hi;
    asm("mov.b64 {%0, %1}, %2;" : "=r"(lo), "=r"(hi) : "l"(v));
    a = __uint_as_float(lo);
    b = __uint_as_float(hi);
}
__device__ __forceinline__ unsigned long long ffma2(unsigned long long a, unsigned long long b,
                                                    unsigned long long c) {
    unsigned long long d;
    asm("fma.rn.f32x2 %0, %1, %2, %3;" : "=l"(d) : "l"(a), "l"(b), "l"(c));
    return d;
}
__device__ __forceinline__ float warp_sum(float v) {
#pragma unroll
    for (int m = 16; m > 0; m >>= 1) v += __shfl_xor_sync(0xffffffffu, v, m);
    return v;
}
__device__ __forceinline__ int ld_idx(const void* p, long long i, int is64) {
    if (is64) return (int)((const long long*)p)[i];
    return ((const int*)p)[i];
}

// ---------------- dtype detection (int32 vs int64 indices) ----------------
__global__ void detect_kernel(const void* ei, const void* bids, int E, int N) {
    // Edge indices: look at odd 32-bit slots in first 128 ints (in-bounds either way).
    // int64 data -> hi words == 0. int32 data -> random values in [0,N), ~never 0.
    const int* p = (const int*)ei;
    int nz = 0;
    for (int k = 1; k < 129; k += 2) nz += (p[k] != 0);
    g_e64 = (nz <= 4) ? 1 : 0;
    // batch_ids: sorted ascending (tail ~ G-1 = 127, nonzero). Sample odd slots near
    // int-index N (in-bounds for both interpretations).
    const int* q = (const int*)bids;
    int nz2 = 0;
    int st = N - 63;
    if (!(st & 1)) st++;
    for (int k = st; k < N; k += 2) nz2 += (q[k] != 0);
    g_b64 = (nz2 <= 4) ? 1 : 0;
}

// ---------------- CSR build ----------------
__global__ void zero_kernel() {
    int i = blockIdx.x * blockDim.x + threadIdx.x;
    if (i < NN + 1) g_deg[i] = 0;
    if (i < GG) g_cntg[i] = 0;
}

__global__ void hist_edges_kernel(const void* ei, int E) {
    int e = blockIdx.x * blockDim.x + threadIdx.x;
    if (e >= E) return;
    int is64 = g_e64;
    int dst = ld_idx(ei, (long long)E + e, is64);
    atomicAdd(&g_deg[dst], 1);
}

__global__ void batch_hist_kernel(const void* bids, int N) {
    int tid = blockIdx.x * blockDim.x + threadIdx.x;
    long long i0 = (long long)tid * 32;
    if (i0 >= N) return;
    int is64 = g_b64;
    long long lim = i0 + 32;
    if (lim > N) lim = N;
    int prev = ld_idx(bids, i0, is64);
    int run = 1;
    for (long long i = i0 + 1; i < lim; i++) {
        int b = ld_idx(bids, i, is64);
        if (b == prev)
            run++;
        else {
            atomicAdd(&g_cntg[prev], run);
            prev = b;
            run = 1;
        }
    }
    atomicAdd(&g_cntg[prev], run);
}

__global__ void scan1_kernel(int n) {
    __shared__ int wsum[32];
    int tid = threadIdx.x, lane = tid & 31, wid = tid >> 5;
    int i = blockIdx.x * 1024 + tid;
    int v = (i < n) ? g_deg[i] : 0;
#pragma unroll
    for (int d = 1; d < 32; d <<= 1) {
        int t = __shfl_up_sync(0xffffffffu, v, d);
        if (lane >= d) v += t;
    }
    if (lane == 31) wsum[wid] = v;
    __syncthreads();
    if (wid == 0) {
        int x = wsum[lane];
#pragma unroll
        for (int d = 1; d < 32; d <<= 1) {
            int t = __shfl_up_sync(0xffffffffu, x, d);
            if (lane >= d) x += t;
        }
        wsum[lane] = x;
    }
    __syncthreads();
    if (wid > 0) v += wsum[wid - 1];
    if (i < n) g_row[i + 1] = v;
    if (tid == 1023) g_bsums[blockIdx.x] = wsum[31];
}

__global__ void scan2_kernel(int nb) {
    int run = 0;
    for (int b = 0; b < nb; b++) {
        int t = g_bsums[b];
        g_bsums[b] = run;
        run += t;
    }
}

__global__ void scan3_kernel(int n) {
    int i = blockIdx.x * 1024 + threadIdx.x;
    if (i < n) {
        int val = g_row[i + 1] + g_bsums[blockIdx.x];
        g_row[i + 1] = val;
        g_cur[i + 1] = val;
    }
    if (blockIdx.x == 0 && threadIdx.x == 0) {
        g_row[0] = 0;
        g_cur[0] = 0;
    }
}

__global__ void fill_kernel(const void* ei, int E) {
    int e = blockIdx.x * blockDim.x + threadIdx.x;
    if (e >= E) return;
    int is64 = g_e64;
    int src = ld_idx(ei, e, is64);
    int dst = ld_idx(ei, (long long)E + e, is64);
    int pos = atomicAdd(&g_cur[dst], 1);
    g_src[pos] = src;
}

// ---------------- projection: [Q|K|V|S] = h @ W + b via packed f32x2 ----------------
template <int FIN>
__global__ void __launch_bounds__(256) proj_kernel(const float* __restrict__ hin,
                                                   const float* __restrict__ Wq, const float* __restrict__ bq,
                                                   const float* __restrict__ Wk, const float* __restrict__ bk,
                                                   const float* __restrict__ Wv, const float* __restrict__ bv,
                                                   const float* __restrict__ Ws, const float* __restrict__ bs,
                                                   int nN) {
    __shared__ __align__(8) float xsh[FIN * 34];  // transposed tile [j][node], stride 34 (8B-aligned pairs)
    int t = threadIdx.x;
    int col = t & 63;
    int sel = t >> 6;  // warp-uniform
    const float* W;
    const float* B;
    float* O;
    if (sel == 0) { W = Wq; B = bq; O = g_Q; }
    else if (sel == 1) { W = Wk; B = bk; O = g_K; }
    else if (sel == 2) { W = Wv; B = bv; O = g_V; }
    else { W = Ws; B = bs; O = g_S; }

    unsigned long long wp[FIN];
#pragma unroll
    for (int j = 0; j < FIN; j++) {
        float w = W[j * 64 + col];
        wp[j] = pack2(w, w);
    }
    float bb = B[col];
    unsigned long long bp = pack2(bb, bb);

    int base = blockIdx.x * 32;
    int cnt = nN - base;
    if (cnt > 32) cnt = 32;
    int total = cnt * FIN;
    for (int idx = t; idx < total; idx += 256) {
        int nd = idx / FIN;
        int j = idx - nd * FIN;
        xsh[j * 34 + nd] = hin[(long long)base * FIN + idx];
    }
    __syncthreads();

    for (int p = 0; p < 32; p += 4) {
        unsigned long long a0 = bp, a1 = bp;
#pragma unroll
        for (int j = 0; j < FIN; j++) {
            unsigned long long x0 = *reinterpret_cast<const unsigned long long*>(&xsh[j * 34 + p]);
            unsigned long long x1 = *reinterpret_cast<const unsigned long long*>(&xsh[j * 34 + p + 2]);
            a0 = ffma2(x0, wp[j], a0);
            a1 = ffma2(x1, wp[j], a1);
        }
        float f0, f1, f2, f3;
        unpack2(a0, f0, f1);
        unpack2(a1, f2, f3);
        int n0 = base + p;
        if (p + 0 < cnt) O[(long long)(n0 + 0) * 64 + col] = f0;
        if (p + 1 < cnt) O[(long long)(n0 + 1) * 64 + col] = f1;
        if (p + 2 < cnt) O[(long long)(n0 + 2) * 64 + col] = f2;
        if (p + 3 < cnt) O[(long long)(n0 + 3) * 64 + col] = f3;
    }
}

// ---------------- per-dst-node online-softmax attention (warp per node) ----------------
__global__ void __launch_bounds__(256) attn_kernel(float* __restrict__ hout, int nN) {
    int node = (blockIdx.x << 3) + (threadIdx.x >> 5);
    if (node >= nN) return;
    int lane = threadIdx.x & 31;
    float2 q2 = *reinterpret_cast<const float2*>(&g_Q[(long long)node * 64 + 2 * lane]);
    int e = g_row[node], end = g_row[node + 1];
    float m = -1e30f, s = 0.f, ax = 0.f, ay = 0.f;
    int srcn = (e < end) ? __ldg(&g_src[e]) : 0;
    for (; e < end; e++) {
        int cur = srcn;
        if (e + 1 < end) srcn = __ldg(&g_src[e + 1]);
        float2 k2 = *reinterpret_cast<const float2*>(&g_K[(long long)cur * 64 + 2 * lane]);
        float2 v2 = *reinterpret_cast<const float2*>(&g_V[(long long)cur * 64 + 2 * lane]);
        float pdot = q2.x * k2.x + q2.y * k2.y;
        pdot = warp_sum(pdot) * 0.125f;  // 1/sqrt(64)
        float mn = fmaxf(m, pdot);
        float cs = __expf(m - mn);
        float w = __expf(pdot - mn);
        s = s * cs + w;
        ax = ax * cs + w * v2.x;
        ay = ay * cs + w * v2.y;
        m = mn;
    }
    float inv = 1.f / (s + 1e-16f);
    float2 sk = *reinterpret_cast<const float2*>(&g_S[(long long)node * 64 + 2 * lane]);
    float2 o;
    o.x = ax * inv + sk.x;
    o.y = ay * inv + sk.y;
    *reinterpret_cast<float2*>(&hout[(long long)node * 64 + 2 * lane]) = o;
}

// ---------------- mean pool per graph + final linear ----------------
__global__ void __launch_bounds__(256) pool_kernel(const float* __restrict__ h,
                                                   const float* __restrict__ Wf,
                                                   const float* __restrict__ bf,
                                                   float* __restrict__ out) {
    __shared__ int ired[256];
    __shared__ float fred[256];
    __shared__ float pooled[64];
    int g = blockIdx.x, t = threadIdx.x;
    ired[t] = (t < g) ? g_cntg[t] : 0;
    __syncthreads();
    for (int sft = 128; sft > 0; sft >>= 1) {
        if (t < sft) ired[t] += ired[t + sft];
        __syncthreads();
    }
    int start = ired[0];
    int cntv = g_cntg[g];
    int dim = t & 63, qd = t >> 6;
    float loc = 0.f;
    for (int i = start + qd; i < start + cntv; i += 4) loc += h[(long long)i * 64 + dim];
    fred[t] = loc;
    __syncthreads();
    if (t < 64)
        pooled[t] = (fred[t] + fred[t + 64] + fred[t + 128] + fred[t + 192]) /
                    fmaxf((float)cntv, 1.f);
    __syncthreads();
    if (t < 5) {
        float acc = bf[t];
#pragma unroll
        for (int d = 0; d < 64; d++) acc += pooled[d] * Wf[d * 5 + t];
        out[g * 5 + t] = acc;
    }
}

// ---------------- launch ----------------
extern "C" void kernel_launch(void* const* d_in, const int* in_sizes, int n_in,
                              void* d_out, int out_size) {
    const float* x = (const float*)d_in[0];
    const void* ei = d_in[1];
    const void* bids = d_in[2];
    const float* Wq0 = (const float*)d_in[3];
    const float* bq0 = (const float*)d_in[4];
    const float* Wk0 = (const float*)d_in[5];
    const float* bk0 = (const float*)d_in[6];
    const float* Wv0 = (const float*)d_in[7];
    const float* bv0 = (const float*)d_in[8];
    const float* Ws0 = (const float*)d_in[9];
    const float* bs0 = (const float*)d_in[10];
    const float* Wqh = (const float*)d_in[11];
    const float* bqh = (const float*)d_in[12];
    const float* Wkh = (const float*)d_in[13];
    const float* bkh = (const float*)d_in[14];
    const float* Wvh = (const float*)d_in[15];
    const float* bvh = (const float*)d_in[16];
    const float* Wsh = (const float*)d_in[17];
    const float* bsh = (const float*)d_in[18];
    const float* Wf = (const float*)d_in[19];
    const float* bf = (const float*)d_in[20];
    float* out = (float*)d_out;

    int N = in_sizes[0] / 16;  // 100000
    int E = in_sizes[1] / 2;   // 1200000 (element count identical for int32/int64 metadata)

    float *h1, *h2;
    cudaGetSymbolAddress((void**)&h1, g_h1);
    cudaGetSymbolAddress((void**)&h2, g_h2);

    // prep: dtype detect + CSR by dst + graph histogram
    detect_kernel<<<1, 1>>>(ei, bids, E, N);
    zero_kernel<<<(NN + 256) / 256, 256>>>();
    hist_edges_kernel<<<(E + 255) / 256, 256>>>(ei, E);
    batch_hist_kernel<<<((N + 31) / 32 + 255) / 256, 256>>>(bids, N);
    int nb1 = (N + 1023) / 1024;
    scan1_kernel<<<nb1, 1024>>>(N);
    scan2_kernel<<<1, 1>>>(nb1);
    scan3_kernel<<<nb1, 1024>>>(N);
    fill_kernel<<<(E + 255) / 256, 256>>>(ei, E);

    int proj_grid = (N + 31) / 32;
    int attn_grid = (N + 7) / 8;

    // layer 0: x (F=16) -> h1
    proj_kernel<16><<<proj_grid, 256>>>(x, Wq0, bq0, Wk0, bk0, Wv0, bv0, Ws0, bs0, N);
    attn_kernel<<<attn_grid, 256>>>(h1, N);

    // hidden layers
    const float* hin = h1;
    float* hout = h2;
    for (int i = 0; i < 3; i++) {
        proj_kernel<64><<<proj_grid, 256>>>(hin, Wqh + (size_t)i * 4096, bqh + (size_t)i * 64,
                                            Wkh + (size_t)i * 4096, bkh + (size_t)i * 64,
                                            Wvh + (size_t)i * 4096, bvh + (size_t)i * 64,
                                            Wsh + (size_t)i * 4096, bsh + (size_t)i * 64, N);
        attn_kernel<<<attn_grid, 256>>>(hout, N);
        const float* tmp = hin;
        hin = hout;
        hout = (float*)tmp;
    }

    // pool + head (final features are in `hin` after the last swap)
    pool_kernel<<<GG, 256>>>(hin, Wf, bf, out);
}

// round 4
// speedup vs baseline: 1.0116x; 1.0116x over previous
#include <cuda_runtime.h>

#define NN 100000
#define EE 1200000
#define GG 128
#define HH 64

// ---------------- static device buffers (no allocation allowed) ----------------
__device__ int g_deg[NN + 1];
__device__ int g_row[NN + 1];
__device__ int g_cur[NN + 1];
__device__ int g_src[EE];
__device__ int g_bsums[256];
__device__ int g_cntg[GG];
__device__ int g_e64, g_b64;
__device__ float g_Q[(size_t)NN * HH];
__device__ float g_K[(size_t)NN * HH];
__device__ float g_V[(size_t)NN * HH];
__device__ float g_S[(size_t)NN * HH];
__device__ float g_h1[(size_t)NN * HH];
__device__ float g_h2[(size_t)NN * HH];

// ---------------- helpers ----------------
__device__ __forceinline__ unsigned long long pack2(float a, float b) {
    unsigned long long r;
    asm("mov.b64 %0, {%1, %2};" : "=l"(r) : "r"(__float_as_uint(a)), "r"(__float_as_uint(b)));
    return r;
}
__device__ __forceinline__ void unpack2(unsigned long long v, float& a, float& b) {
    unsigned int lo, hi;
    asm("mov.b64 {%0, %1}, %2;" : "=r"(lo), "=r"(hi) : "l"(v));
    a = __uint_as_float(lo);
    b = __uint_as_float(hi);
}
__device__ __forceinline__ unsigned long long ffma2(unsigned long long a, unsigned long long b,
                                                    unsigned long long c) {
    unsigned long long d;
    asm("fma.rn.f32x2 %0, %1, %2, %3;" : "=l"(d) : "l"(a), "l"(b), "l"(c));
    return d;
}
__device__ __forceinline__ int ld_idx(const void* p, long long i, int is64) {
    if (is64) return (int)((const long long*)p)[i];
    return ((const int*)p)[i];
}

// ---------------- dtype detection (int32 vs int64 indices) ----------------
__global__ void detect_kernel(const void* ei, const void* bids, int E, int N) {
    const int* p = (const int*)ei;
    int nz = 0;
    for (int k = 1; k < 129; k += 2) nz += (p[k] != 0);
    g_e64 = (nz <= 4) ? 1 : 0;
    const int* q = (const int*)bids;
    int nz2 = 0;
    int st = N - 63;
    if (!(st & 1)) st++;
    for (int k = st; k < N; k += 2) nz2 += (q[k] != 0);
    g_b64 = (nz2 <= 4) ? 1 : 0;
}

// ---------------- CSR build ----------------
__global__ void zero_kernel() {
    int i = blockIdx.x * blockDim.x + threadIdx.x;
    if (i < NN + 1) g_deg[i] = 0;
    if (i < GG) g_cntg[i] = 0;
}

__global__ void hist_edges_kernel(const void* ei, int E) {
    int e = blockIdx.x * blockDim.x + threadIdx.x;
    if (e >= E) return;
    int is64 = g_e64;
    int dst = ld_idx(ei, (long long)E + e, is64);
    atomicAdd(&g_deg[dst], 1);
}

__global__ void batch_hist_kernel(const void* bids, int N) {
    int tid = blockIdx.x * blockDim.x + threadIdx.x;
    long long i0 = (long long)tid * 32;
    if (i0 >= N) return;
    int is64 = g_b64;
    long long lim = i0 + 32;
    if (lim > N) lim = N;
    int prev = ld_idx(bids, i0, is64);
    int run = 1;
    for (long long i = i0 + 1; i < lim; i++) {
        int b = ld_idx(bids, i, is64);
        if (b == prev)
            run++;
        else {
            atomicAdd(&g_cntg[prev], run);
            prev = b;
            run = 1;
        }
    }
    atomicAdd(&g_cntg[prev], run);
}

__global__ void scan1_kernel(int n) {
    __shared__ int wsum[32];
    int tid = threadIdx.x, lane = tid & 31, wid = tid >> 5;
    int i = blockIdx.x * 1024 + tid;
    int v = (i < n) ? g_deg[i] : 0;
#pragma unroll
    for (int d = 1; d < 32; d <<= 1) {
        int t = __shfl_up_sync(0xffffffffu, v, d);
        if (lane >= d) v += t;
    }
    if (lane == 31) wsum[wid] = v;
    __syncthreads();
    if (wid == 0) {
        int x = wsum[lane];
#pragma unroll
        for (int d = 1; d < 32; d <<= 1) {
            int t = __shfl_up_sync(0xffffffffu, x, d);
            if (lane >= d) x += t;
        }
        wsum[lane] = x;
    }
    __syncthreads();
    if (wid > 0) v += wsum[wid - 1];
    if (i < n) g_row[i + 1] = v;
    if (tid == 1023) g_bsums[blockIdx.x] = wsum[31];
}

__global__ void scan2_kernel(int nb) {
    int run = 0;
    for (int b = 0; b < nb; b++) {
        int t = g_bsums[b];
        g_bsums[b] = run;
        run += t;
    }
}

__global__ void scan3_kernel(int n) {
    int i = blockIdx.x * 1024 + threadIdx.x;
    if (i < n) {
        int val = g_row[i + 1] + g_bsums[blockIdx.x];
        g_row[i + 1] = val;
        g_cur[i + 1] = val;
    }
    if (blockIdx.x == 0 && threadIdx.x == 0) {
        g_row[0] = 0;
        g_cur[0] = 0;
    }
}

__global__ void fill_kernel(const void* ei, int E) {
    int e = blockIdx.x * blockDim.x + threadIdx.x;
    if (e >= E) return;
    int is64 = g_e64;
    int src = ld_idx(ei, e, is64);
    int dst = ld_idx(ei, (long long)E + e, is64);
    int pos = atomicAdd(&g_cur[dst], 1);
    g_src[pos] = src;
}

// ---------------- projection: [Q|K|V|S] = h @ W + b, LDS.128 + 4 FFMA2 chains ----------------
template <int FIN>
__global__ void __launch_bounds__(256) proj_kernel(const float* __restrict__ hin,
                                                   const float* __restrict__ Wq, const float* __restrict__ bq,
                                                   const float* __restrict__ Wk, const float* __restrict__ bk,
                                                   const float* __restrict__ Wv, const float* __restrict__ bv,
                                                   const float* __restrict__ Ws, const float* __restrict__ bs,
                                                   int nN) {
    __shared__ __align__(16) float xsh[FIN * 36];  // transposed tile [j][node], stride 36 (16B-aligned quads)
    int t = threadIdx.x;
    int col = t & 63;
    int sel = t >> 6;  // warp-uniform: 0=Q 1=K 2=V 3=S
    const float* W;
    const float* B;
    float* O;
    if (sel == 0) { W = Wq; B = bq; O = g_Q; }
    else if (sel == 1) { W = Wk; B = bk; O = g_K; }
    else if (sel == 2) { W = Wv; B = bv; O = g_V; }
    else { W = Ws; B = bs; O = g_S; }

    unsigned long long wp[FIN];
#pragma unroll
    for (int j = 0; j < FIN; j++) {
        float w = W[j * 64 + col];
        wp[j] = pack2(w, w);
    }
    float bb = B[col];
    unsigned long long bp = pack2(bb, bb);

    int base = blockIdx.x * 32;
    int cnt = nN - base;
    if (cnt > 32) cnt = 32;
    int total = cnt * FIN;
    for (int idx = t; idx < total; idx += 256) {
        int nd = idx / FIN;
        int j = idx - nd * FIN;
        xsh[j * 36 + nd] = hin[(long long)base * FIN + idx];
    }
    __syncthreads();

    for (int p = 0; p < 32; p += 8) {
        unsigned long long a0 = bp, a1 = bp, a2 = bp, a3 = bp;
#pragma unroll
        for (int j = 0; j < FIN; j++) {
            ulonglong2 x01 = *reinterpret_cast<const ulonglong2*>(&xsh[j * 36 + p]);
            ulonglong2 x23 = *reinterpret_cast<const ulonglong2*>(&xsh[j * 36 + p + 4]);
            a0 = ffma2(x01.x, wp[j], a0);
            a1 = ffma2(x01.y, wp[j], a1);
            a2 = ffma2(x23.x, wp[j], a2);
            a3 = ffma2(x23.y, wp[j], a3);
        }
        float f[8];
        unpack2(a0, f[0], f[1]);
        unpack2(a1, f[2], f[3]);
        unpack2(a2, f[4], f[5]);
        unpack2(a3, f[6], f[7]);
#pragma unroll
        for (int u = 0; u < 8; u++)
            if (p + u < cnt) O[(long long)(base + p + u) * 64 + col] = f[u];
    }
}

// ---------------- attention: 2 edges/warp, 16 lanes/edge, fp32 float4 gathers ----------------
__global__ void __launch_bounds__(256) attn_kernel(float* __restrict__ hout, int nN) {
    int node = (blockIdx.x << 3) + (threadIdx.x >> 5);
    if (node >= nN) return;
    int lane = threadIdx.x & 31;
    int sub = lane >> 4;   // which edge of the pair
    int sl = lane & 15;    // dim group: dims 4sl..4sl+3
    float4 q4 = *reinterpret_cast<const float4*>(&g_Q[(long long)node * 64 + 4 * sl]);
    int start = g_row[node], end = g_row[node + 1];
    float m = -1e30f, s = 0.f;
    float4 a = {0.f, 0.f, 0.f, 0.f};
    for (int e = start; e < end; e += 2) {
        int ee = e + sub;
        bool act = ee < end;
        int cur = act ? __ldg(&g_src[ee]) : 0;
        float4 k4 = *reinterpret_cast<const float4*>(&g_K[(long long)cur * 64 + 4 * sl]);
        float4 v4 = *reinterpret_cast<const float4*>(&g_V[(long long)cur * 64 + 4 * sl]);
        float pdot = q4.x * k4.x + q4.y * k4.y + q4.z * k4.z + q4.w * k4.w;
#pragma unroll
        for (int off = 8; off; off >>= 1) pdot += __shfl_xor_sync(0xffffffffu, pdot, off);
        pdot *= 0.125f;  // 1/sqrt(64)
        if (!act) pdot = -1e30f;
        float mn = fmaxf(m, pdot);
        float cs = __expf(m - mn);
        float w = act ? __expf(pdot - mn) : 0.f;
        s = s * cs + w;
        a.x = a.x * cs + w * v4.x;
        a.y = a.y * cs + w * v4.y;
        a.z = a.z * cs + w * v4.z;
        a.w = a.w * cs + w * v4.w;
        m = mn;
    }
    // merge the two half-warp softmax streams (exact in fp32)
    float m2 = __shfl_xor_sync(0xffffffffu, m, 16);
    float s2 = __shfl_xor_sync(0xffffffffu, s, 16);
    float bx = __shfl_xor_sync(0xffffffffu, a.x, 16);
    float by = __shfl_xor_sync(0xffffffffu, a.y, 16);
    float bz = __shfl_xor_sync(0xffffffffu, a.z, 16);
    float bw = __shfl_xor_sync(0xffffffffu, a.w, 16);
    float M = fmaxf(m, m2);
    float c1 = __expf(m - M);
    float c2 = __expf(m2 - M);
    s = s * c1 + s2 * c2;
    a.x = a.x * c1 + bx * c2;
    a.y = a.y * c1 + by * c2;
    a.z = a.z * c1 + bz * c2;
    a.w = a.w * c1 + bw * c2;
    float inv = 1.f / (s + 1e-16f);
    if (sub == 0) {
        float4 sk = *reinterpret_cast<const float4*>(&g_S[(long long)node * 64 + 4 * sl]);
        float4 o;
        o.x = a.x * inv + sk.x;
        o.y = a.y * inv + sk.y;
        o.z = a.z * inv + sk.z;
        o.w = a.w * inv + sk.w;
        *reinterpret_cast<float4*>(&hout[(long long)node * 64 + 4 * sl]) = o;
    }
}

// ---------------- mean pool per graph + final linear ----------------
__global__ void __launch_bounds__(256) pool_kernel(const float* __restrict__ h,
                                                   const float* __restrict__ Wf,
                                                   const float* __restrict__ bf,
                                                   float* __restrict__ out) {
    __shared__ int ired[256];
    __shared__ float fred[256];
    __shared__ float pooled[64];
    int g = blockIdx.x, t = threadIdx.x;
    ired[t] = (t < g) ? g_cntg[t] : 0;
    __syncthreads();
    for (int sft = 128; sft > 0; sft >>= 1) {
        if (t < sft) ired[t] += ired[t + sft];
        __syncthreads();
    }
    int start = ired[0];
    int cntv = g_cntg[g];
    int dim = t & 63, qd = t >> 6;
    float loc = 0.f;
    for (int i = start + qd; i < start + cntv; i += 4) loc += h[(long long)i * 64 + dim];
    fred[t] = loc;
    __syncthreads();
    if (t < 64)
        pooled[t] = (fred[t] + fred[t + 64] + fred[t + 128] + fred[t + 192]) /
                    fmaxf((float)cntv, 1.f);
    __syncthreads();
    if (t < 5) {
        float acc = bf[t];
#pragma unroll
        for (int d = 0; d < 64; d++) acc += pooled[d] * Wf[d * 5 + t];
        out[g * 5 + t] = acc;
    }
}

// ---------------- launch ----------------
extern "C" void kernel_launch(void* const* d_in, const int* in_sizes, int n_in,
                              void* d_out, int out_size) {
    const float* x = (const float*)d_in[0];
    const void* ei = d_in[1];
    const void* bids = d_in[2];
    const float* Wq0 = (const float*)d_in[3];
    const float* bq0 = (const float*)d_in[4];
    const float* Wk0 = (const float*)d_in[5];
    const float* bk0 = (const float*)d_in[6];
    const float* Wv0 = (const float*)d_in[7];
    const float* bv0 = (const float*)d_in[8];
    const float* Ws0 = (const float*)d_in[9];
    const float* bs0 = (const float*)d_in[10];
    const float* Wqh = (const float*)d_in[11];
    const float* bqh = (const float*)d_in[12];
    const float* Wkh = (const float*)d_in[13];
    const float* bkh = (const float*)d_in[14];
    const float* Wvh = (const float*)d_in[15];
    const float* bvh = (const float*)d_in[16];
    const float* Wsh = (const float*)d_in[17];
    const float* bsh = (const float*)d_in[18];
    const float* Wf = (const float*)d_in[19];
    const float* bf = (const float*)d_in[20];
    float* out = (float*)d_out;

    int N = in_sizes[0] / 16;  // 100000
    int E = in_sizes[1] / 2;   // 1200000

    float *h1, *h2;
    cudaGetSymbolAddress((void**)&h1, g_h1);
    cudaGetSymbolAddress((void**)&h2, g_h2);

    // prep: dtype detect + CSR by dst + graph histogram
    detect_kernel<<<1, 1>>>(ei, bids, E, N);
    zero_kernel<<<(NN + 256) / 256, 256>>>();
    hist_edges_kernel<<<(E + 255) / 256, 256>>>(ei, E);
    batch_hist_kernel<<<((N + 31) / 32 + 255) / 256, 256>>>(bids, N);
    int nb1 = (N + 1023) / 1024;
    scan1_kernel<<<nb1, 1024>>>(N);
    scan2_kernel<<<1, 1>>>(nb1);
    scan3_kernel<<<nb1, 1024>>>(N);
    fill_kernel<<<(E + 255) / 256, 256>>>(ei, E);

    int proj_grid = (N + 31) / 32;
    int attn_grid = (N + 7) / 8;

    // layer 0: x (F=16) -> h1
    proj_kernel<16><<<proj_grid, 256>>>(x, Wq0, bq0, Wk0, bk0, Wv0, bv0, Ws0, bs0, N);
    attn_kernel<<<attn_grid, 256>>>(h1, N);

    // hidden layers
    const float* hin = h1;
    float* hout = h2;
    for (int i = 0; i < 3; i++) {
        proj_kernel<64><<<proj_grid, 256>>>(hin, Wqh + (size_t)i * 4096, bqh + (size_t)i * 64,
                                            Wkh + (size_t)i * 4096, bkh + (size_t)i * 64,
                                            Wvh + (size_t)i * 4096, bvh + (size_t)i * 64,
                                            Wsh + (size_t)i * 4096, bsh + (size_t)i * 64, N);
        attn_kernel<<<attn_grid, 256>>>(hout, N);
        const float* tmp = hin;
        hin = hout;
        hout = (float*)tmp;
    }

    // pool + head
    pool_kernel<<<GG, 256>>>(hin, Wf, bf, out);
}